// round 14
// baseline (speedup 1.0000x reference)
#include <cuda_runtime.h>
#include <cuda_fp16.h>
#include <cstdint>

// Problem constants (fixed by reference setup_inputs): 40000 nodes, E=640000.
#define NN 40000
#define FF 128
#define CC 40
#define EE 640000
#define SCAN_NB ((NN + 255) / 256)   // 157

#define XA_STRIDE 132
#define WS_STRIDE 132
#define LAYER_SMEM ((64 * XA_STRIDE + 32 * WS_STRIDE) * 4)   // 50688 B

__device__ float  g_deg[NN];
__device__ int    g_cnt[NN];
__device__ int    g_off[NN];
__device__ int    g_cur[NN];
__device__ int    g_bsum[SCAN_NB];
__device__ int    g_boff[SCAN_NB];
__device__ int    g_csr_src[EE];
__device__ __half g_xh[NN * FF];     // layer-1 gather operand (x * dinv)
__device__ __half g_xh2[NN * FF];    // layer-2 gather operand (h1 * dinv)
__device__ float  g_buf1[NN * FF];   // h2 fp32
__device__ int    g_is64;

__device__ __forceinline__ int edge_idx(const int* ei, int pos) {
    if (g_is64) return (int)((const long long*)ei)[pos];
    return ei[pos];
}

// ---------------------------------------------------------------------------
// init: zero counts (all blocks) + dtype detect (block 0, warp 0)
// ---------------------------------------------------------------------------
__global__ void k_init(const int* __restrict__ ei) {
    int i = blockIdx.x * blockDim.x + threadIdx.x;
    if (i < NN) g_cnt[i] = 0;
    if (blockIdx.x == 0 && threadIdx.x < 32) {
        int lane = threadIdx.x;
        int nz = 0;
        for (int k = lane; k < 512; k += 32) nz |= (ei[2 * k + 1] != 0);
        unsigned any = __ballot_sync(0xFFFFFFFFu, nz);
        if (lane == 0) g_is64 = (any == 0u);
    }
}

__global__ void k_cnt_acc(const int* __restrict__ ei) {
    int i = blockIdx.x * blockDim.x + threadIdx.x;
    if (i < EE) atomicAdd(&g_cnt[edge_idx(ei, EE + i)], 1);
}

// ---------------------------------------------------------------------------
// 3-phase scan
// ---------------------------------------------------------------------------
__device__ __forceinline__ int block_excl_scan(int v, int* smem32, int tid,
                                               int* tot) {
    int lane = tid & 31, wid = tid >> 5;
    int x = v;
#pragma unroll
    for (int s = 1; s < 32; s <<= 1) {
        int y = __shfl_up_sync(0xFFFFFFFFu, x, s);
        if (lane >= s) x += y;
    }
    if (lane == 31) smem32[wid] = x;
    __syncthreads();
    if (wid == 0) {
        int w = (lane < 8) ? smem32[lane] : 0;
#pragma unroll
        for (int s = 1; s < 8; s <<= 1) {
            int y = __shfl_up_sync(0xFFFFFFFFu, w, s);
            if (lane >= s) w += y;
        }
        if (lane < 8) smem32[lane] = w;
    }
    __syncthreads();
    int woff = (wid > 0) ? smem32[wid - 1] : 0;
    *tot = smem32[7];
    return woff + (x - v);
}

__global__ void k_scan_a() {
    __shared__ int sm[32];
    int tid = threadIdx.x;
    int i = blockIdx.x * 256 + tid;
    int v = (i < NN) ? g_cnt[i] : 0;
    int tot;
    block_excl_scan(v, sm, tid, &tot);
    if (tid == 0) g_bsum[blockIdx.x] = tot;
}

__global__ void k_scan_b() {
    __shared__ int sm[32];
    int tid = threadIdx.x;
    int v = (tid < SCAN_NB) ? g_bsum[tid] : 0;
    int tot;
    int ex = block_excl_scan(v, sm, tid, &tot);
    if (tid < SCAN_NB) g_boff[tid] = ex;
}

// scan_c + dinv + x->fp16 conversion (warp-per-row, coalesced)
__global__ void k_scan_ct(const float* __restrict__ X) {
    __shared__ int sm[32];
    int tid = threadIdx.x;
    int i = blockIdx.x * 256 + tid;
    int c = (i < NN) ? g_cnt[i] : 0;
    int tot;
    int ex = block_excl_scan(c, sm, tid, &tot);
    if (i < NN) {
        int off = g_boff[blockIdx.x] + ex;
        g_off[i] = off;
        g_cur[i] = off;
        g_deg[i] = rsqrtf((float)(c + 1));
    }
    __syncthreads();   // g_deg for this block's nodes now visible block-wide

    int wid = tid >> 5, lane = tid & 31;
    int rbase = blockIdx.x * 256 + wid * 32;
#pragma unroll
    for (int it = 0; it < 32; it++) {
        int r = rbase + it;
        if (r >= NN) break;
        float s = g_deg[r];
        float4 v = *(const float4*)&X[(size_t)r * FF + lane * 4];
        __half2 h0 = __floats2half2_rn(v.x * s, v.y * s);
        __half2 h1 = __floats2half2_rn(v.z * s, v.w * s);
        uint2 u;
        u.x = *(unsigned*)&h0;
        u.y = *(unsigned*)&h1;
        *(uint2*)&g_xh[(size_t)r * FF + lane * 4] = u;
    }
}

__global__ void k_fill(const int* __restrict__ ei) {
    int e = blockIdx.x * blockDim.x + threadIdx.x;
    if (e >= EE) return;
    int s = edge_idx(ei, e);
    int d = edge_idx(ei, EE + e);
    int pos = atomicAdd(&g_cur[d], 1);
    g_csr_src[pos] = s;
}

// ---------------------------------------------------------------------------
// Fused layer: phase 1 CSR SpMM (gather fp16 rows -> fp32 agg in smem),
// phase 2 tiled GEMM + ReLU.  EPI=0: out fp16*dinv -> g_xh2 (for next spmm).
// EPI=1: out fp32 -> Y (for head).
// ---------------------------------------------------------------------------
__device__ __forceinline__ void h8add(uint2 u, float& a0, float& a1,
                                      float& a2, float& a3) {
    float2 f0 = __half22float2(*(__half2*)&u.x);
    float2 f1 = __half22float2(*(__half2*)&u.y);
    a0 += f0.x; a1 += f0.y; a2 += f1.x; a3 += f1.y;
}

template <int EPI>
__global__ void k_layer(const __half* __restrict__ xin,
                        const float* __restrict__ W,
                        const float* __restrict__ b,
                        __half* __restrict__ outh,
                        float* __restrict__ outf) {
    extern __shared__ float smem[];
    float* xa = smem;                       // [64][XA_STRIDE]
    float* ws = smem + 64 * XA_STRIDE;      // [32][WS_STRIDE]

    int tid = threadIdx.x;
    int wid = tid >> 5, lane = tid & 31;
    int row0 = blockIdx.x * 64;
    const uint2* base = (const uint2*)xin;  // row = 32 uint2

    // ---- phase 1: aggregate 8 rows per warp ----
#pragma unroll
    for (int p = 0; p < 8; p++) {
        int rl = wid * 8 + p;
        int r = row0 + rl;
        uint2 us = __ldg(&base[(size_t)r * 32 + lane]);   // self loop
        float a0 = 0, a1 = 0, a2 = 0, a3 = 0;
        h8add(us, a0, a1, a2, a3);

        int beg = g_off[r];
        int end = beg + g_cnt[r];
        int j = beg;
        for (; j + 3 < end; j += 4) {
            int s0 = __ldg(&g_csr_src[j]);
            int s1 = __ldg(&g_csr_src[j + 1]);
            int s2 = __ldg(&g_csr_src[j + 2]);
            int s3 = __ldg(&g_csr_src[j + 3]);
            uint2 u0 = __ldg(&base[(size_t)s0 * 32 + lane]);
            uint2 u1 = __ldg(&base[(size_t)s1 * 32 + lane]);
            uint2 u2 = __ldg(&base[(size_t)s2 * 32 + lane]);
            uint2 u3 = __ldg(&base[(size_t)s3 * 32 + lane]);
            h8add(u0, a0, a1, a2, a3);
            h8add(u1, a0, a1, a2, a3);
            h8add(u2, a0, a1, a2, a3);
            h8add(u3, a0, a1, a2, a3);
        }
        for (; j < end; j++) {
            int s0 = __ldg(&g_csr_src[j]);
            uint2 u0 = __ldg(&base[(size_t)s0 * 32 + lane]);
            h8add(u0, a0, a1, a2, a3);
        }
        float dd = g_deg[r];
        float* xr = xa + rl * XA_STRIDE + lane * 4;
        xr[0] = a0 * dd; xr[1] = a1 * dd; xr[2] = a2 * dd; xr[3] = a3 * dd;
    }
    __syncthreads();

    // ---- phase 2: GEMM (validated R8 skeleton, xa in place) ----
    int tx = tid & 31;
    int ty = tid >> 5;
    float acc[8][4];
#pragma unroll
    for (int i = 0; i < 8; i++)
#pragma unroll
        for (int j = 0; j < 4; j++) acc[i][j] = 0.0f;

    for (int kb = 0; kb < FF; kb += 32) {
        if (kb) __syncthreads();
#pragma unroll
        for (int u = tid; u < 1024; u += 256) {
            int f = u >> 3;
            int c4 = (u & 7) * 4;
            float4 v = *(const float4*)&W[f * FF + kb + c4];
            ws[(c4 + 0) * WS_STRIDE + f] = v.x;
            ws[(c4 + 1) * WS_STRIDE + f] = v.y;
            ws[(c4 + 2) * WS_STRIDE + f] = v.z;
            ws[(c4 + 3) * WS_STRIDE + f] = v.w;
        }
        __syncthreads();

#pragma unroll
        for (int k = 0; k < 32; k++) {
            float4 wv = *(const float4*)&ws[k * WS_STRIDE + tx * 4];
            float xv[8];
#pragma unroll
            for (int i = 0; i < 8; i++)
                xv[i] = xa[(ty * 8 + i) * XA_STRIDE + kb + k];
#pragma unroll
            for (int i = 0; i < 8; i++) {
                acc[i][0] = fmaf(xv[i], wv.x, acc[i][0]);
                acc[i][1] = fmaf(xv[i], wv.y, acc[i][1]);
                acc[i][2] = fmaf(xv[i], wv.z, acc[i][2]);
                acc[i][3] = fmaf(xv[i], wv.w, acc[i][3]);
            }
        }
    }

    float4 bv = *(const float4*)&b[tx * 4];
#pragma unroll
    for (int i = 0; i < 8; i++) {
        int r = row0 + ty * 8 + i;
        float o0 = fmaxf(acc[i][0] + bv.x, 0.0f);
        float o1 = fmaxf(acc[i][1] + bv.y, 0.0f);
        float o2 = fmaxf(acc[i][2] + bv.z, 0.0f);
        float o3 = fmaxf(acc[i][3] + bv.w, 0.0f);
        if (EPI == 0) {
            float dd = g_deg[r];
            __half2 h0 = __floats2half2_rn(o0 * dd, o1 * dd);
            __half2 h1 = __floats2half2_rn(o2 * dd, o3 * dd);
            uint2 u;
            u.x = *(unsigned*)&h0;
            u.y = *(unsigned*)&h1;
            *(uint2*)&outh[(size_t)r * FF + tx * 4] = u;
        } else {
            *(float4*)&outf[(size_t)r * FF + tx * 4] =
                make_float4(o0, o1, o2, o3);
        }
    }
}

// ---------------------------------------------------------------------------
// Tiled head (validated R11): out = X @ Wl^T + bl.
// ---------------------------------------------------------------------------
__global__ void k_head2(const float* __restrict__ X,
                        const float* __restrict__ W,
                        const float* __restrict__ b,
                        float* __restrict__ Y) {
    __shared__ float xs[32][132];
    __shared__ float ws[128][44];

    int tid = threadIdx.x;
    int row0 = blockIdx.x * 32;

#pragma unroll
    for (int u = tid; u < 1024; u += 256) {
        int r = u >> 5;
        int c4 = (u & 31) * 4;
        float4 v = *(const float4*)&X[(row0 + r) * FF + c4];
        xs[r][c4 + 0] = v.x; xs[r][c4 + 1] = v.y;
        xs[r][c4 + 2] = v.z; xs[r][c4 + 3] = v.w;
    }
#pragma unroll
    for (int u = tid; u < 1280; u += 256) {
        int c = u >> 5;
        int k4 = (u & 31) * 4;
        float4 v = *(const float4*)&W[c * FF + k4];
        ws[k4 + 0][c] = v.x; ws[k4 + 1][c] = v.y;
        ws[k4 + 2][c] = v.z; ws[k4 + 3][c] = v.w;
    }
    __syncthreads();

    int tx = tid & 7;
    int ty = tid >> 3;

    float acc[5] = {0, 0, 0, 0, 0};
#pragma unroll 8
    for (int k = 0; k < FF; k++) {
        float x0 = xs[ty][k];
#pragma unroll
        for (int j = 0; j < 5; j++)
            acc[j] = fmaf(x0, ws[k][tx * 5 + j], acc[j]);
    }

    int r = row0 + ty;
#pragma unroll
    for (int j = 0; j < 5; j++) {
        int c = tx * 5 + j;
        Y[r * CC + c] = acc[j] + b[c];
    }
}

// ---------------------------------------------------------------------------
// Launch
// ---------------------------------------------------------------------------
extern "C" void kernel_launch(void* const* d_in, const int* in_sizes, int n_in,
                              void* d_out, int out_size) {
    const float* x   = (const float*)d_in[0];
    const int*   ei  = (const int*)d_in[1];
    const float* W1  = (const float*)d_in[2];
    const float* b1  = (const float*)d_in[3];
    const float* W2  = (const float*)d_in[4];
    const float* b2  = (const float*)d_in[5];
    const float* Wl  = (const float*)d_in[6];
    const float* bl  = (const float*)d_in[7];
    float*       out = (float*)d_out;

    static bool attr_set = false;
    if (!attr_set) {
        cudaFuncSetAttribute(k_layer<0>,
            cudaFuncAttributeMaxDynamicSharedMemorySize, LAYER_SMEM);
        cudaFuncSetAttribute(k_layer<1>,
            cudaFuncAttributeMaxDynamicSharedMemorySize, LAYER_SMEM);
        attr_set = true;
    }

    __half* xh;   cudaGetSymbolAddress((void**)&xh,   g_xh);
    __half* xh2;  cudaGetSymbolAddress((void**)&xh2,  g_xh2);
    float*  buf1; cudaGetSymbolAddress((void**)&buf1, g_buf1);

    // CSR build + dinv + fp16 input
    k_init<<<SCAN_NB, 256>>>(ei);
    k_cnt_acc<<<(EE + 255) / 256, 256>>>(ei);
    k_scan_a<<<SCAN_NB, 256>>>();
    k_scan_b<<<1, 256>>>();
    k_scan_ct<<<SCAN_NB, 256>>>(x);
    k_fill<<<(EE + 255) / 256, 256>>>(ei);

    // fused layers
    k_layer<0><<<NN / 64, 256, LAYER_SMEM>>>(xh,  W1, b1, xh2, nullptr);
    k_layer<1><<<NN / 64, 256, LAYER_SMEM>>>(xh2, W2, b2, nullptr, buf1);

    // head
    k_head2<<<NN / 32, 256>>>(buf1, Wl, bl, out);
}

// round 15
// speedup vs baseline: 1.7065x; 1.7065x over previous
#include <cuda_runtime.h>
#include <cuda_fp16.h>
#include <cstdint>

// Problem constants (fixed by reference setup_inputs): 40000 nodes, E=640000.
#define NN 40000
#define FF 128
#define CC 40
#define EE 640000
#define SCAN_NB ((NN + 255) / 256)   // 157

__device__ float  g_deg[NN];
__device__ int    g_cnt[NN];
__device__ int    g_off[NN];
__device__ int    g_cur[NN];
__device__ int    g_bsum[SCAN_NB];
__device__ int    g_boff[SCAN_NB];
__device__ int    g_csr_src[EE];
__device__ __half g_xh[NN * FF];     // layer-1 gather operand (x * dinv)
__device__ __half g_xh2[NN * FF];    // layer-2 gather operand (h1 * dinv)
__device__ __half g_xa[NN * FF];     // spmm output (GEMM A operand, fp16)
__device__ float  g_buf1[NN * FF];   // h2 fp32 (head input)
__device__ uint2  g_wfrag[2 * 8 * 16 * 32];  // [layer][kstep][nchunk][lane]
__device__ int    g_is64;

__device__ __forceinline__ int edge_idx(const int* ei, int pos) {
    if (g_is64) return (int)((const long long*)ei)[pos];
    return ei[pos];
}

__device__ __forceinline__ unsigned packh2(float a, float b) {
    __half2 h = __floats2half2_rn(a, b);
    return *(unsigned*)&h;
}

// ---------------------------------------------------------------------------
// init: zero counts + dtype detect + pack W1/W2 into mma B-fragment order.
// B-frag (m16n8k16.row.col): lane l, n = chunk*8 + l/4, k = step*16 + (l%4)*2;
// b0 = {B[k][n],B[k+1][n]} = {W[n][k],W[n][k+1]};  b1 = same with k+8.
// ---------------------------------------------------------------------------
__global__ void k_init(const int* __restrict__ ei,
                       const float* __restrict__ W1,
                       const float* __restrict__ W2) {
    int i = blockIdx.x * blockDim.x + threadIdx.x;
    if (i < NN) g_cnt[i] = 0;
    if (i < 2 * 8 * 16 * 32) {
        int L = i >> 12;
        int rem = i & 4095;
        int s = rem >> 9;
        int c = (rem >> 5) & 15;
        int l = rem & 31;
        int n = c * 8 + (l >> 2);
        int k = s * 16 + ((l & 3) << 1);
        const float* W = L ? W2 : W1;
        uint2 u;
        u.x = packh2(W[n * FF + k],     W[n * FF + k + 1]);
        u.y = packh2(W[n * FF + k + 8], W[n * FF + k + 9]);
        g_wfrag[i] = u;
    }
    if (blockIdx.x == 0 && threadIdx.x < 32) {
        int lane = threadIdx.x;
        int nz = 0;
        for (int k = lane; k < 512; k += 32) nz |= (ei[2 * k + 1] != 0);
        unsigned any = __ballot_sync(0xFFFFFFFFu, nz);
        if (lane == 0) g_is64 = (any == 0u);
    }
}

__global__ void k_cnt_acc(const int* __restrict__ ei) {
    int i = blockIdx.x * blockDim.x + threadIdx.x;
    if (i < EE) atomicAdd(&g_cnt[edge_idx(ei, EE + i)], 1);
}

// ---------------------------------------------------------------------------
// 3-phase scan (validated R13)
// ---------------------------------------------------------------------------
__device__ __forceinline__ int block_excl_scan(int v, int* smem32, int tid,
                                               int* tot) {
    int lane = tid & 31, wid = tid >> 5;
    int x = v;
#pragma unroll
    for (int s = 1; s < 32; s <<= 1) {
        int y = __shfl_up_sync(0xFFFFFFFFu, x, s);
        if (lane >= s) x += y;
    }
    if (lane == 31) smem32[wid] = x;
    __syncthreads();
    if (wid == 0) {
        int w = (lane < 8) ? smem32[lane] : 0;
#pragma unroll
        for (int s = 1; s < 8; s <<= 1) {
            int y = __shfl_up_sync(0xFFFFFFFFu, w, s);
            if (lane >= s) w += y;
        }
        if (lane < 8) smem32[lane] = w;
    }
    __syncthreads();
    int woff = (wid > 0) ? smem32[wid - 1] : 0;
    *tot = smem32[7];
    return woff + (x - v);
}

__global__ void k_scan_a() {
    __shared__ int sm[32];
    int tid = threadIdx.x;
    int i = blockIdx.x * 256 + tid;
    int v = (i < NN) ? g_cnt[i] : 0;
    int tot;
    block_excl_scan(v, sm, tid, &tot);
    if (tid == 0) g_bsum[blockIdx.x] = tot;
}

__global__ void k_scan_b() {
    __shared__ int sm[32];
    int tid = threadIdx.x;
    int v = (tid < SCAN_NB) ? g_bsum[tid] : 0;
    int tot;
    int ex = block_excl_scan(v, sm, tid, &tot);
    if (tid < SCAN_NB) g_boff[tid] = ex;
}

// scan_c + dinv + x->fp16 (validated R13)
__global__ void k_scan_ct(const float* __restrict__ X) {
    __shared__ int sm[32];
    int tid = threadIdx.x;
    int i = blockIdx.x * 256 + tid;
    int c = (i < NN) ? g_cnt[i] : 0;
    int tot;
    int ex = block_excl_scan(c, sm, tid, &tot);
    if (i < NN) {
        int off = g_boff[blockIdx.x] + ex;
        g_off[i] = off;
        g_cur[i] = off;
        g_deg[i] = rsqrtf((float)(c + 1));
    }
    __syncthreads();

    int wid = tid >> 5, lane = tid & 31;
    int rbase = blockIdx.x * 256 + wid * 32;
#pragma unroll
    for (int it = 0; it < 32; it++) {
        int r = rbase + it;
        if (r >= NN) break;
        float s = g_deg[r];
        float4 v = *(const float4*)&X[(size_t)r * FF + lane * 4];
        uint2 u;
        u.x = packh2(v.x * s, v.y * s);
        u.y = packh2(v.z * s, v.w * s);
        *(uint2*)&g_xh[(size_t)r * FF + lane * 4] = u;
    }
}

__global__ void k_fill(const int* __restrict__ ei) {
    int e = blockIdx.x * blockDim.x + threadIdx.x;
    if (e >= EE) return;
    int s = edge_idx(ei, e);
    int d = edge_idx(ei, EE + e);
    int pos = atomicAdd(&g_cur[d], 1);
    g_csr_src[pos] = s;
}

// ---------------------------------------------------------------------------
// CSR SpMM (R13 structure, validated): warp per dst row; fp16 in, fp16 out.
// out[d] = fp16( dinv[d] * (sum_{s in N(d)} in[s] + in[d]) )
// ---------------------------------------------------------------------------
__device__ __forceinline__ void h8add(uint2 u, float& a0, float& a1,
                                      float& a2, float& a3) {
    float2 f0 = __half22float2(*(__half2*)&u.x);
    float2 f1 = __half22float2(*(__half2*)&u.y);
    a0 += f0.x; a1 += f0.y; a2 += f1.x; a3 += f1.y;
}

__global__ void k_spmm_h(const __half* __restrict__ xin) {
    int w = blockIdx.x * 8 + (threadIdx.x >> 5);   // dst node
    if (w >= NN) return;
    int lane = threadIdx.x & 31;
    const uint2* base = (const uint2*)xin;

    uint2 us = __ldg(&base[(size_t)w * 32 + lane]);
    float a0 = 0, a1 = 0, a2 = 0, a3 = 0;
    h8add(us, a0, a1, a2, a3);

    int beg = g_off[w];
    int end = beg + g_cnt[w];
    int j = beg;
    for (; j + 3 < end; j += 4) {
        int s0 = __ldg(&g_csr_src[j]);
        int s1 = __ldg(&g_csr_src[j + 1]);
        int s2 = __ldg(&g_csr_src[j + 2]);
        int s3 = __ldg(&g_csr_src[j + 3]);
        uint2 u0 = __ldg(&base[(size_t)s0 * 32 + lane]);
        uint2 u1 = __ldg(&base[(size_t)s1 * 32 + lane]);
        uint2 u2 = __ldg(&base[(size_t)s2 * 32 + lane]);
        uint2 u3 = __ldg(&base[(size_t)s3 * 32 + lane]);
        h8add(u0, a0, a1, a2, a3);
        h8add(u1, a0, a1, a2, a3);
        h8add(u2, a0, a1, a2, a3);
        h8add(u3, a0, a1, a2, a3);
    }
    for (; j < end; j++) {
        int s0 = __ldg(&g_csr_src[j]);
        uint2 u0 = __ldg(&base[(size_t)s0 * 32 + lane]);
        h8add(u0, a0, a1, a2, a3);
    }

    float dd = g_deg[w];
    uint2 o;
    o.x = packh2(a0 * dd, a1 * dd);
    o.y = packh2(a2 * dd, a3 * dd);
    *(uint2*)&g_xa[(size_t)w * FF + lane * 4] = o;
}

// ---------------------------------------------------------------------------
// Tensor-core GEMM: Y = relu(Xa @ W^T + b) via mma.sync m16n8k16 f16->f32.
// Block: 64 rows x 128 cols, 8 warps = 4 row-groups x 2 col-groups.
// Warp: 16 rows x 64 cols = per k-step {1 ldmatrix.x4 A} x {8 mma}.
// EPI=0: out = fp16(relu * dinv) -> g_xh2.  EPI=1: out fp32 -> outf.
// ---------------------------------------------------------------------------
#define XS_STRIDE 136   // halves; 272B row stride -> LDSM conflict-free

template <int EPI>
__global__ void k_gemm_mma(const __half* __restrict__ Xa,
                           int wlayer,
                           const float* __restrict__ b,
                           float* __restrict__ outf) {
    __shared__ __half Xs[64 * XS_STRIDE];

    int tid = threadIdx.x;
    int warp = tid >> 5, lane = tid & 31;
    int row0 = blockIdx.x * 64;

    // stage X tile: 64 rows x 128 halves (1024 uint4, 4 per thread)
#pragma unroll
    for (int u = tid; u < 1024; u += 256) {
        int r = u >> 4;
        int q = u & 15;             // 16B chunk (8 halves)
        uint4 v = *(const uint4*)&Xa[(size_t)(row0 + r) * FF + q * 8];
        *(uint4*)&Xs[r * XS_STRIDE + q * 8] = v;
    }
    __syncthreads();

    int rg = warp & 3;              // row group: rows rg*16..+15
    int cg = warp >> 2;             // col group: cols cg*64..+63
    int rowL = rg * 16;

    float acc[8][4];
#pragma unroll
    for (int c = 0; c < 8; c++)
#pragma unroll
        for (int j = 0; j < 4; j++) acc[c][j] = 0.0f;

    // ldmatrix lane address: grp 0:(lr,0) 1:(lr+8,0) 2:(lr,8) 3:(lr+8,8)
    int grp = lane >> 3;
    int lr = lane & 7;
    int mrow = rowL + lr + ((grp & 1) << 3);
    int kadd = (grp & 2) << 2;      // 0 or 8
    unsigned xs_base = (unsigned)__cvta_generic_to_shared(Xs);

#pragma unroll
    for (int s = 0; s < 8; s++) {
        unsigned addr = xs_base + (mrow * XS_STRIDE + s * 16 + kadd) * 2;
        unsigned a0, a1, a2, a3;
        asm volatile(
            "ldmatrix.sync.aligned.m8n8.x4.shared.b16 {%0,%1,%2,%3}, [%4];"
            : "=r"(a0), "=r"(a1), "=r"(a2), "=r"(a3) : "r"(addr));

        const uint2* wf = &g_wfrag[((wlayer * 8 + s) * 16 + cg * 8) * 32 + lane];
#pragma unroll
        for (int c = 0; c < 8; c++) {
            uint2 bf = __ldg(&wf[c * 32]);
            asm volatile(
                "mma.sync.aligned.m16n8k16.row.col.f32.f16.f16.f32 "
                "{%0,%1,%2,%3}, {%4,%5,%6,%7}, {%8,%9}, {%0,%1,%2,%3};"
                : "+f"(acc[c][0]), "+f"(acc[c][1]),
                  "+f"(acc[c][2]), "+f"(acc[c][3])
                : "r"(a0), "r"(a1), "r"(a2), "r"(a3),
                  "r"(bf.x), "r"(bf.y));
        }
    }

    // epilogue: c0,c1 -> (row lane/4, cols +0,+1); c2,c3 -> row+8
    int rA = row0 + rowL + (lane >> 2);
    int rB = rA + 8;
#pragma unroll
    for (int c = 0; c < 8; c++) {
        int cb = cg * 64 + c * 8 + ((lane & 3) << 1);
        float bb0 = __ldg(&b[cb]);
        float bb1 = __ldg(&b[cb + 1]);
        float o0 = fmaxf(acc[c][0] + bb0, 0.0f);
        float o1 = fmaxf(acc[c][1] + bb1, 0.0f);
        float o2 = fmaxf(acc[c][2] + bb0, 0.0f);
        float o3 = fmaxf(acc[c][3] + bb1, 0.0f);
        if (EPI == 0) {
            float dA = g_deg[rA], dB = g_deg[rB];
            *(unsigned*)&g_xh2[(size_t)rA * FF + cb] = packh2(o0 * dA, o1 * dA);
            *(unsigned*)&g_xh2[(size_t)rB * FF + cb] = packh2(o2 * dB, o3 * dB);
        } else {
            *(float2*)&outf[(size_t)rA * FF + cb] = make_float2(o0, o1);
            *(float2*)&outf[(size_t)rB * FF + cb] = make_float2(o2, o3);
        }
    }
}

// ---------------------------------------------------------------------------
// Tiled head (validated R11): out = X @ Wl^T + bl.
// ---------------------------------------------------------------------------
__global__ void k_head2(const float* __restrict__ X,
                        const float* __restrict__ W,
                        const float* __restrict__ b,
                        float* __restrict__ Y) {
    __shared__ float xs[32][132];
    __shared__ float ws[128][44];

    int tid = threadIdx.x;
    int row0 = blockIdx.x * 32;

#pragma unroll
    for (int u = tid; u < 1024; u += 256) {
        int r = u >> 5;
        int c4 = (u & 31) * 4;
        float4 v = *(const float4*)&X[(row0 + r) * FF + c4];
        xs[r][c4 + 0] = v.x; xs[r][c4 + 1] = v.y;
        xs[r][c4 + 2] = v.z; xs[r][c4 + 3] = v.w;
    }
#pragma unroll
    for (int u = tid; u < 1280; u += 256) {
        int c = u >> 5;
        int k4 = (u & 31) * 4;
        float4 v = *(const float4*)&W[c * FF + k4];
        ws[k4 + 0][c] = v.x; ws[k4 + 1][c] = v.y;
        ws[k4 + 2][c] = v.z; ws[k4 + 3][c] = v.w;
    }
    __syncthreads();

    int tx = tid & 7;
    int ty = tid >> 3;

    float acc[5] = {0, 0, 0, 0, 0};
#pragma unroll 8
    for (int k = 0; k < FF; k++) {
        float x0 = xs[ty][k];
#pragma unroll
        for (int j = 0; j < 5; j++)
            acc[j] = fmaf(x0, ws[k][tx * 5 + j], acc[j]);
    }

    int r = row0 + ty;
#pragma unroll
    for (int j = 0; j < 5; j++) {
        int c = tx * 5 + j;
        Y[r * CC + c] = acc[j] + b[c];
    }
}

// ---------------------------------------------------------------------------
// Launch
// ---------------------------------------------------------------------------
extern "C" void kernel_launch(void* const* d_in, const int* in_sizes, int n_in,
                              void* d_out, int out_size) {
    const float* x   = (const float*)d_in[0];
    const int*   ei  = (const int*)d_in[1];
    const float* W1  = (const float*)d_in[2];
    const float* b1  = (const float*)d_in[3];
    const float* W2  = (const float*)d_in[4];
    const float* b2  = (const float*)d_in[5];
    const float* Wl  = (const float*)d_in[6];
    const float* bl  = (const float*)d_in[7];
    float*       out = (float*)d_out;

    __half* xh;   cudaGetSymbolAddress((void**)&xh,   g_xh);
    __half* xh2;  cudaGetSymbolAddress((void**)&xh2,  g_xh2);
    __half* xa;   cudaGetSymbolAddress((void**)&xa,   g_xa);
    float*  buf1; cudaGetSymbolAddress((void**)&buf1, g_buf1);

    // CSR build + dinv + fp16 input + W fragment packing
    k_init<<<SCAN_NB, 256>>>(ei, W1, W2);
    k_cnt_acc<<<(EE + 255) / 256, 256>>>(ei);
    k_scan_a<<<SCAN_NB, 256>>>();
    k_scan_b<<<1, 256>>>();
    k_scan_ct<<<SCAN_NB, 256>>>(x);
    k_fill<<<(EE + 255) / 256, 256>>>(ei);

    // layer 1
    k_spmm_h<<<(NN + 7) / 8, 256>>>(xh);                    // -> g_xa
    k_gemm_mma<0><<<NN / 64, 256>>>(xa, 0, b1, nullptr);    // -> g_xh2

    // layer 2
    k_spmm_h<<<(NN + 7) / 8, 256>>>(xh2);                   // -> g_xa
    k_gemm_mma<1><<<NN / 64, 256>>>(xa, 1, b2, buf1);       // -> buf1 fp32

    // head
    k_head2<<<NN / 32, 256>>>(buf1, Wl, bl, out);
}

// round 16
// speedup vs baseline: 1.9846x; 1.1630x over previous
#include <cuda_runtime.h>
#include <cuda_fp16.h>
#include <cstdint>

// Problem constants (fixed by reference setup_inputs): 40000 nodes, E=640000.
#define NN 40000
#define FF 128
#define CC 40
#define EE 640000
#define SCAN_NB ((NN + 255) / 256)   // 157

#define HS_STRIDE 132
#define WLS_OFF   (64 * HS_STRIDE)                    // floats
#define HEAD_SMEM ((64 * HS_STRIDE + 128 * 44) * 4)   // 56320 B

__device__ float  g_deg[NN];
__device__ int    g_cnt[NN];
__device__ int    g_off[NN];
__device__ int    g_cur[NN];
__device__ int    g_bsum[SCAN_NB];
__device__ int    g_scan_ready;
__device__ int    g_csr_src[EE];
__device__ __half g_xh[NN * FF];     // layer-1 gather operand (x * dinv)
__device__ __half g_xh2[NN * FF];    // layer-2 gather operand (h1 * dinv)
__device__ __half g_xa[NN * FF];     // spmm output (GEMM A operand, fp16)
__device__ uint2  g_wfrag[2 * 8 * 16 * 32];  // [layer][kstep][nchunk][lane]
__device__ int    g_is64;

__device__ __forceinline__ int edge_idx(const int* ei, int pos) {
    if (g_is64) return (int)((const long long*)ei)[pos];
    return ei[pos];
}

__device__ __forceinline__ unsigned packh2(float a, float b) {
    __half2 h = __floats2half2_rn(a, b);
    return *(unsigned*)&h;
}

// ---------------------------------------------------------------------------
// init: zero counts/flag + dtype detect + pack W1/W2 into mma B-frag order.
// ---------------------------------------------------------------------------
__global__ void k_init(const int* __restrict__ ei,
                       const float* __restrict__ W1,
                       const float* __restrict__ W2) {
    int i = blockIdx.x * blockDim.x + threadIdx.x;
    if (i < NN) g_cnt[i] = 0;
    if (i == 0) g_scan_ready = 0;
    if (i < 2 * 8 * 16 * 32) {
        int L = i >> 12;
        int rem = i & 4095;
        int s = rem >> 9;
        int c = (rem >> 5) & 15;
        int l = rem & 31;
        int n = c * 8 + (l >> 2);
        int k = s * 16 + ((l & 3) << 1);
        const float* W = L ? W2 : W1;
        uint2 u;
        u.x = packh2(W[n * FF + k],     W[n * FF + k + 1]);
        u.y = packh2(W[n * FF + k + 8], W[n * FF + k + 9]);
        g_wfrag[i] = u;
    }
    if (blockIdx.x == 0 && threadIdx.x < 32) {
        int lane = threadIdx.x;
        int nz = 0;
        for (int k = lane; k < 512; k += 32) nz |= (ei[2 * k + 1] != 0);
        unsigned any = __ballot_sync(0xFFFFFFFFu, nz);
        if (lane == 0) g_is64 = (any == 0u);
    }
}

__global__ void k_cnt_acc(const int* __restrict__ ei) {
    int i = blockIdx.x * blockDim.x + threadIdx.x;
    if (i < EE) atomicAdd(&g_cnt[edge_idx(ei, EE + i)], 1);
}

// ---------------------------------------------------------------------------
// Single-pass scan + dinv + x->fp16.  All 157 blocks are co-resident:
// publish aggregate, spin until all published, sum predecessors locally.
// ---------------------------------------------------------------------------
__device__ __forceinline__ int block_excl_scan(int v, int* smem32, int tid,
                                               int* tot) {
    int lane = tid & 31, wid = tid >> 5;
    int x = v;
#pragma unroll
    for (int s = 1; s < 32; s <<= 1) {
        int y = __shfl_up_sync(0xFFFFFFFFu, x, s);
        if (lane >= s) x += y;
    }
    if (lane == 31) smem32[wid] = x;
    __syncthreads();
    if (wid == 0) {
        int w = (lane < 8) ? smem32[lane] : 0;
#pragma unroll
        for (int s = 1; s < 8; s <<= 1) {
            int y = __shfl_up_sync(0xFFFFFFFFu, w, s);
            if (lane >= s) w += y;
        }
        if (lane < 8) smem32[lane] = w;
    }
    __syncthreads();
    int woff = (wid > 0) ? smem32[wid - 1] : 0;
    *tot = smem32[7];
    return woff + (x - v);
}

__global__ void k_scan_all(const float* __restrict__ X) {
    __shared__ int sm[32];
    __shared__ int rsm[9];
    int tid = threadIdx.x;
    int bid = blockIdx.x;
    int i = bid * 256 + tid;

    int c = (i < NN) ? g_cnt[i] : 0;
    int tot;
    int ex = block_excl_scan(c, sm, tid, &tot);

    if (tid == 0) {
        g_bsum[bid] = tot;
        __threadfence();
        atomicAdd(&g_scan_ready, 1);
        while (atomicAdd(&g_scan_ready, 0) < SCAN_NB) {}
    }
    __syncthreads();

    // parallel sum of g_bsum[0..bid-1]
    int ssum = 0;
    for (int k = tid; k < bid; k += 256) ssum += g_bsum[k];
#pragma unroll
    for (int o = 16; o; o >>= 1) ssum += __shfl_down_sync(0xFFFFFFFFu, ssum, o);
    if ((tid & 31) == 0) rsm[tid >> 5] = ssum;
    __syncthreads();
    if (tid == 0) {
        int t = 0;
#pragma unroll
        for (int w = 0; w < 8; w++) t += rsm[w];
        rsm[8] = t;
    }
    __syncthreads();
    int boff = rsm[8];

    if (i < NN) {
        int off = boff + ex;
        g_off[i] = off;
        g_cur[i] = off;
        g_deg[i] = rsqrtf((float)(c + 1));
    }
    __syncthreads();

    // x -> fp16 * dinv  (warp-per-row, coalesced)
    int wid = tid >> 5, lane = tid & 31;
    int rbase = bid * 256 + wid * 32;
#pragma unroll
    for (int it = 0; it < 32; it++) {
        int r = rbase + it;
        if (r >= NN) break;
        float s = g_deg[r];
        float4 v = *(const float4*)&X[(size_t)r * FF + lane * 4];
        uint2 u;
        u.x = packh2(v.x * s, v.y * s);
        u.y = packh2(v.z * s, v.w * s);
        *(uint2*)&g_xh[(size_t)r * FF + lane * 4] = u;
    }
}

__global__ void k_fill(const int* __restrict__ ei) {
    int e = blockIdx.x * blockDim.x + threadIdx.x;
    if (e >= EE) return;
    int s = edge_idx(ei, e);
    int d = edge_idx(ei, EE + e);
    int pos = atomicAdd(&g_cur[d], 1);
    g_csr_src[pos] = s;
}

// ---------------------------------------------------------------------------
// CSR SpMM (validated R13/R15): warp per dst row; fp16 in, fp16 out -> g_xa.
// ---------------------------------------------------------------------------
__device__ __forceinline__ void h8add(uint2 u, float& a0, float& a1,
                                      float& a2, float& a3) {
    float2 f0 = __half22float2(*(__half2*)&u.x);
    float2 f1 = __half22float2(*(__half2*)&u.y);
    a0 += f0.x; a1 += f0.y; a2 += f1.x; a3 += f1.y;
}

__global__ void k_spmm_h(const __half* __restrict__ xin) {
    int w = blockIdx.x * 8 + (threadIdx.x >> 5);
    if (w >= NN) return;
    int lane = threadIdx.x & 31;
    const uint2* base = (const uint2*)xin;

    uint2 us = __ldg(&base[(size_t)w * 32 + lane]);
    float a0 = 0, a1 = 0, a2 = 0, a3 = 0;
    h8add(us, a0, a1, a2, a3);

    int beg = g_off[w];
    int end = beg + g_cnt[w];
    int j = beg;
    for (; j + 3 < end; j += 4) {
        int s0 = __ldg(&g_csr_src[j]);
        int s1 = __ldg(&g_csr_src[j + 1]);
        int s2 = __ldg(&g_csr_src[j + 2]);
        int s3 = __ldg(&g_csr_src[j + 3]);
        uint2 u0 = __ldg(&base[(size_t)s0 * 32 + lane]);
        uint2 u1 = __ldg(&base[(size_t)s1 * 32 + lane]);
        uint2 u2 = __ldg(&base[(size_t)s2 * 32 + lane]);
        uint2 u3 = __ldg(&base[(size_t)s3 * 32 + lane]);
        h8add(u0, a0, a1, a2, a3);
        h8add(u1, a0, a1, a2, a3);
        h8add(u2, a0, a1, a2, a3);
        h8add(u3, a0, a1, a2, a3);
    }
    for (; j < end; j++) {
        int s0 = __ldg(&g_csr_src[j]);
        uint2 u0 = __ldg(&base[(size_t)s0 * 32 + lane]);
        h8add(u0, a0, a1, a2, a3);
    }

    float dd = g_deg[w];
    uint2 o;
    o.x = packh2(a0 * dd, a1 * dd);
    o.y = packh2(a2 * dd, a3 * dd);
    *(uint2*)&g_xa[(size_t)w * FF + lane * 4] = o;
}

// ---------------------------------------------------------------------------
// Shared mma core (validated R15): 64x128 tile, 8 warps = 4 rg x 2 cg.
// Produces acc[8][4] per warp.
// ---------------------------------------------------------------------------
#define XS_STRIDE 136

#define MMA_CORE(XSPTR, WLAYER)                                               \
    int warp = tid >> 5, lane = tid & 31;                                     \
    int row0 = blockIdx.x * 64;                                               \
    _Pragma("unroll")                                                         \
    for (int u = tid; u < 1024; u += 256) {                                   \
        int r = u >> 4;                                                       \
        int q = u & 15;                                                       \
        uint4 v = *(const uint4*)&Xa[(size_t)(row0 + r) * FF + q * 8];        \
        *(uint4*)&XSPTR[r * XS_STRIDE + q * 8] = v;                           \
    }                                                                         \
    __syncthreads();                                                          \
    int rg = warp & 3;                                                        \
    int cg = warp >> 2;                                                       \
    int rowL = rg * 16;                                                       \
    float acc[8][4];                                                          \
    _Pragma("unroll")                                                         \
    for (int c = 0; c < 8; c++)                                               \
        _Pragma("unroll")                                                     \
        for (int j = 0; j < 4; j++) acc[c][j] = 0.0f;                         \
    int grp = lane >> 3;                                                      \
    int lr = lane & 7;                                                        \
    int mrow = rowL + lr + ((grp & 1) << 3);                                  \
    int kadd = (grp & 2) << 2;                                                \
    unsigned xs_base = (unsigned)__cvta_generic_to_shared(XSPTR);             \
    _Pragma("unroll")                                                         \
    for (int s = 0; s < 8; s++) {                                             \
        unsigned addr = xs_base + (mrow * XS_STRIDE + s * 16 + kadd) * 2;     \
        unsigned a0, a1, a2, a3;                                              \
        asm volatile(                                                         \
            "ldmatrix.sync.aligned.m8n8.x4.shared.b16 {%0,%1,%2,%3}, [%4];"   \
            : "=r"(a0), "=r"(a1), "=r"(a2), "=r"(a3) : "r"(addr));            \
        const uint2* wf =                                                     \
            &g_wfrag[(((WLAYER) * 8 + s) * 16 + cg * 8) * 32 + lane];         \
        _Pragma("unroll")                                                     \
        for (int c = 0; c < 8; c++) {                                         \
            uint2 bf = __ldg(&wf[c * 32]);                                    \
            asm volatile(                                                     \
                "mma.sync.aligned.m16n8k16.row.col.f32.f16.f16.f32 "          \
                "{%0,%1,%2,%3}, {%4,%5,%6,%7}, {%8,%9}, {%0,%1,%2,%3};"       \
                : "+f"(acc[c][0]), "+f"(acc[c][1]),                           \
                  "+f"(acc[c][2]), "+f"(acc[c][3])                            \
                : "r"(a0), "r"(a1), "r"(a2), "r"(a3),                         \
                  "r"(bf.x), "r"(bf.y));                                      \
        }                                                                     \
    }

// Layer-1 GEMM: out = fp16(relu(.) * dinv) -> g_xh2
__global__ void k_gemm_mma0(const __half* __restrict__ Xa,
                            const float* __restrict__ b) {
    __shared__ __half Xs[64 * XS_STRIDE];
    int tid = threadIdx.x;
    MMA_CORE(Xs, 0)

    int rA = row0 + rowL + (lane >> 2);
    int rB = rA + 8;
    float dA = g_deg[rA], dB = g_deg[rB];
#pragma unroll
    for (int c = 0; c < 8; c++) {
        int cb = cg * 64 + c * 8 + ((lane & 3) << 1);
        float bb0 = __ldg(&b[cb]);
        float bb1 = __ldg(&b[cb + 1]);
        float o0 = fmaxf(acc[c][0] + bb0, 0.0f);
        float o1 = fmaxf(acc[c][1] + bb1, 0.0f);
        float o2 = fmaxf(acc[c][2] + bb0, 0.0f);
        float o3 = fmaxf(acc[c][3] + bb1, 0.0f);
        *(unsigned*)&g_xh2[(size_t)rA * FF + cb] = packh2(o0 * dA, o1 * dA);
        *(unsigned*)&g_xh2[(size_t)rB * FF + cb] = packh2(o2 * dB, o3 * dB);
    }
}

// Layer-2 GEMM fused with head: h2 (smem) @ Wl^T + bl -> out
__global__ void k_gemm_head(const __half* __restrict__ Xa,
                            const float* __restrict__ b,
                            const float* __restrict__ Wl,
                            const float* __restrict__ bl,
                            float* __restrict__ out) {
    extern __shared__ float dsm[];
    __half* Xs = (__half*)dsm;                 // phase A (dies after mma)
    float* hs  = dsm;                          // [64][HS_STRIDE]
    float* wls = dsm + WLS_OFF;                // [128][44]

    int tid = threadIdx.x;
    MMA_CORE(Xs, 1)
    __syncthreads();   // Xs dead; safe to overwrite with hs

    // write h2 tile to smem
    {
        int rA = rowL + (lane >> 2);
        int rB = rA + 8;
#pragma unroll
        for (int c = 0; c < 8; c++) {
            int cb = cg * 64 + c * 8 + ((lane & 3) << 1);
            float bb0 = __ldg(&b[cb]);
            float bb1 = __ldg(&b[cb + 1]);
            hs[rA * HS_STRIDE + cb]     = fmaxf(acc[c][0] + bb0, 0.0f);
            hs[rA * HS_STRIDE + cb + 1] = fmaxf(acc[c][1] + bb1, 0.0f);
            hs[rB * HS_STRIDE + cb]     = fmaxf(acc[c][2] + bb0, 0.0f);
            hs[rB * HS_STRIDE + cb + 1] = fmaxf(acc[c][3] + bb1, 0.0f);
        }
    }
    // stage Wl transposed: wls[k][c]
#pragma unroll
    for (int u = tid; u < 1280; u += 256) {
        int c = u >> 5;
        int k4 = (u & 31) * 4;
        float4 v = *(const float4*)&Wl[c * FF + k4];
        wls[(k4 + 0) * 44 + c] = v.x;
        wls[(k4 + 1) * 44 + c] = v.y;
        wls[(k4 + 2) * 44 + c] = v.z;
        wls[(k4 + 3) * 44 + c] = v.w;
    }
    __syncthreads();

    // head: 2 rows x 5 cols per thread
    int tx = tid & 7;
    int ty = tid >> 3;
#pragma unroll
    for (int rr = 0; rr < 64; rr += 32) {
        int r = rr + ty;
        float hacc[5] = {0, 0, 0, 0, 0};
#pragma unroll 8
        for (int k = 0; k < FF; k++) {
            float x0 = hs[r * HS_STRIDE + k];
#pragma unroll
            for (int j = 0; j < 5; j++)
                hacc[j] = fmaf(x0, wls[k * 44 + tx * 5 + j], hacc[j]);
        }
        int gr = row0 + r;
#pragma unroll
        for (int j = 0; j < 5; j++) {
            int c = tx * 5 + j;
            out[gr * CC + c] = hacc[j] + __ldg(&bl[c]);
        }
    }
}

// ---------------------------------------------------------------------------
// Launch
// ---------------------------------------------------------------------------
extern "C" void kernel_launch(void* const* d_in, const int* in_sizes, int n_in,
                              void* d_out, int out_size) {
    const float* x   = (const float*)d_in[0];
    const int*   ei  = (const int*)d_in[1];
    const float* W1  = (const float*)d_in[2];
    const float* b1  = (const float*)d_in[3];
    const float* W2  = (const float*)d_in[4];
    const float* b2  = (const float*)d_in[5];
    const float* Wl  = (const float*)d_in[6];
    const float* bl  = (const float*)d_in[7];
    float*       out = (float*)d_out;

    cudaFuncSetAttribute(k_gemm_head,
        cudaFuncAttributeMaxDynamicSharedMemorySize, HEAD_SMEM);

    __half* xh;  cudaGetSymbolAddress((void**)&xh,  g_xh);
    __half* xh2; cudaGetSymbolAddress((void**)&xh2, g_xh2);
    __half* xa;  cudaGetSymbolAddress((void**)&xa,  g_xa);

    k_init<<<SCAN_NB, 256>>>(ei, W1, W2);
    k_cnt_acc<<<(EE + 255) / 256, 256>>>(ei);
    k_scan_all<<<SCAN_NB, 256>>>(x);
    k_fill<<<(EE + 255) / 256, 256>>>(ei);

    k_spmm_h<<<(NN + 7) / 8, 256>>>(xh);                 // -> g_xa
    k_gemm_mma0<<<NN / 64, 256>>>(xa, b1);               // -> g_xh2
    k_spmm_h<<<(NN + 7) / 8, 256>>>(xh2);                // -> g_xa
    k_gemm_head<<<NN / 64, 256, HEAD_SMEM>>>(xa, b2, Wl, bl, out);
}